// round 16
// baseline (speedup 1.0000x reference)
#include <cuda_runtime.h>
#include <cuda_fp16.h>
#include <cstdint>

// ---------------- problem constants ----------------
#define BT    16
#define D_CH  1056
#define OH    57
#define OW    87
#define MAXN  13
#define KK    5
#define NFB   1024
#define NA    6
#define R_TOT 208
#define KDIM  26400
#define KPAD_E 26624              // 832 * 32
#define KSPLIT 32
#define KT_E   (KPAD_E/32/KSPLIT) // 26 k-chunks (of 32) per split
#define KPAD_U 1024
#define KSPLIT_U 4
#define KT_U   (KPAD_U/32/KSPLIT_U) // 8
#define NPAIR_B 156
#define NPAIR   2496
#define MROWS 256
#define RSPLIT 128                 // roi/GEMM M-row split point (2 M-tiles)

// ---------------- scratch (device globals; zero-initialized) ----------------
__device__ __align__(16) __half g_Ae [MROWS * KPAD_E];
__device__ __align__(16) __half g_Be [NFB * KPAD_E];
__device__ __align__(16) __half g_Bu [2 * NFB * KPAD_U];
__device__ __align__(16) __half g_f  [MROWS * NFB];
__device__ float g_fraw[R_TOT * NFB];
__device__ float g_part[KSPLIT * R_TOT * NFB];
__device__ float g_UVp [KSPLIT_U * R_TOT * 2 * NFB];
__device__ float g_UV  [R_TOT * 2 * NFB];

// ---------------- helpers ----------------
__device__ __forceinline__ uint32_t smem_u32(const void* p) {
    uint32_t a;
    asm("{ .reg .u64 t; cvta.to.shared.u64 t, %1; cvt.u32.u64 %0, t; }"
        : "=r"(a) : "l"(p));
    return a;
}
__device__ __forceinline__ void cp16(uint32_t dst, const void* src) {
    asm volatile("cp.async.cg.shared.global [%0], [%1], 16;" :: "r"(dst), "l"(src));
}
#define CP_COMMIT() asm volatile("cp.async.commit_group;" ::: "memory")

#define LDM4(R, addr) \
    asm volatile("ldmatrix.sync.aligned.m8n8.x4.shared.b16 {%0,%1,%2,%3}, [%4];" \
        : "=r"((R)[0]), "=r"((R)[1]), "=r"((R)[2]), "=r"((R)[3]) : "r"(addr))

#define MMA(D, A, B0, B1) \
    asm volatile("mma.sync.aligned.m16n8k16.row.col.f32.f16.f16.f32 " \
        "{%0,%1,%2,%3}, {%4,%5,%6,%7}, {%8,%9}, {%0,%1,%2,%3};" \
        : "+f"((D)[0]), "+f"((D)[1]), "+f"((D)[2]), "+f"((D)[3]) \
        : "r"((A)[0]), "r"((A)[1]), "r"((A)[2]), "r"((A)[3]), "r"(B0), "r"(B1))

// =====================================================================
// converters (vectorized: 8 elems/thread, 16B stores)
// =====================================================================
__global__ __launch_bounds__(256) void conv_wemb(
    const float* __restrict__ W, __half* __restrict__ o)
{
    int f = blockIdx.y;
    int k0 = (blockIdx.x * 256 + threadIdx.x) * 8;   // grid.x = 13
    __half h[8];
    const float* src = W + (size_t)f * KDIM + k0;
    if (k0 + 8 <= KDIM) {
        float4 v0 = *(const float4*)src;
        float4 v1 = *(const float4*)(src + 4);
        h[0] = __float2half_rn(v0.x); h[1] = __float2half_rn(v0.y);
        h[2] = __float2half_rn(v0.z); h[3] = __float2half_rn(v0.w);
        h[4] = __float2half_rn(v1.x); h[5] = __float2half_rn(v1.y);
        h[6] = __float2half_rn(v1.z); h[7] = __float2half_rn(v1.w);
    } else {
#pragma unroll
        for (int i = 0; i < 8; ++i)
            h[i] = (k0 + i < KDIM) ? __float2half_rn(src[i]) : __ushort_as_half(0);
    }
    *(uint4*)(o + (size_t)f * KPAD_E + k0) = *(const uint4*)h;
}

__global__ __launch_bounds__(128) void conv_wi1(
    const float* __restrict__ W, __half* __restrict__ o)
{
    int f = blockIdx.x;
    int k0 = threadIdx.x * 8;
    const float* src = (f < NFB) ? W + (size_t)f * (2 * NFB) + k0
                                 : W + (size_t)(f - NFB) * (2 * NFB) + NFB + k0;
    float4 v0 = *(const float4*)src;
    float4 v1 = *(const float4*)(src + 4);
    __half h[8];
    h[0] = __float2half_rn(v0.x); h[1] = __float2half_rn(v0.y);
    h[2] = __float2half_rn(v0.z); h[3] = __float2half_rn(v0.w);
    h[4] = __float2half_rn(v1.x); h[5] = __float2half_rn(v1.y);
    h[6] = __float2half_rn(v1.z); h[7] = __float2half_rn(v1.w);
    *(uint4*)(o + (size_t)f * KPAD_U + k0) = *(const uint4*)h;
}

// =====================================================================
// ROI align -> fp16 A operand (point math hoisted; rBase selects row slab)
// =====================================================================
__global__ __launch_bounds__(256) void roi_align_kernel(
    const float* __restrict__ feat, const float* __restrict__ boxes,
    __half* __restrict__ ah, int rBase)
{
    int r  = blockIdx.y + rBase;
    int d0 = blockIdx.x * 32;
    int b  = r / MAXN;
    int tid = threadIdx.x;

    __shared__ int4   sidx[25];
    __shared__ float4 swgt[25];
    __shared__ float  tile[32][25];

    if (tid < 25) {
        const float* bx = boxes + r * 4;
        float x1 = bx[0], y1 = bx[1], x2 = bx[2], y2 = bx[3];
        float bw = (x2 - x1) * (1.0f / KK);
        float bh = (y2 - y1) * (1.0f / KK);
        int iy = tid / 5, jx = tid % 5;
        float xs = x1 + (jx + 0.5f) * bw;
        float ys = y1 + (iy + 0.5f) * bh;
        float x0f = floorf(xs), y0f = floorf(ys);
        float lx = xs - x0f, ly = ys - y0f;
        int x0 = (int)x0f, y0 = (int)y0f;
        int x0i = min(max(x0, 0), OW - 1);
        int x1i = min(max(x0 + 1, 0), OW - 1);
        int y0i = min(max(y0, 0), OH - 1);
        int y1i = min(max(y0 + 1, 0), OH - 1);
        sidx[tid] = make_int4(y0i * OW + x0i, y0i * OW + x1i,
                              y1i * OW + x0i, y1i * OW + x1i);
        float wy0 = 1.f - ly, wx0 = 1.f - lx;
        swgt[tid] = make_float4(wy0 * wx0, wy0 * lx, ly * wx0, ly * lx);
    }
    __syncthreads();

    int dl = tid >> 3, pl = tid & 7;
    const float* fb = feat + (size_t)(b * D_CH + d0 + dl) * (OH * OW);
    for (int p = pl; p < 25; p += 8) {
        int4 ix = sidx[p];
        float4 w = swgt[p];
        tile[dl][p] = fb[ix.x] * w.x + fb[ix.y] * w.y
                    + fb[ix.z] * w.z + fb[ix.w] * w.w;
    }
    __syncthreads();

    size_t base = (size_t)r * KPAD_E + d0 * 25;  // even offset
    const float* src = &tile[0][0];
    for (int t = tid; t < 400; t += 256) {
        *(__half2*)(ah + base + 2 * t) =
            __halves2half2(__float2half_rn(src[2 * t]), __float2half_rn(src[2 * t + 1]));
    }
    if (blockIdx.x == 0 && tid < 28) {
        uint4 z = make_uint4(0, 0, 0, 0);
        *(uint4*)(ah + (size_t)r * KPAD_E + KDIM + tid * 8) = z;
    }
}

// =====================================================================
// HMMA fp16 GEMM (R11 measured-best config): C[z] = A * B^T
//   block tile 64(M) x 128(N) x 32(K), 8 warps (2M x 4N, warp tile 32x32),
//   3-stage cp.async pipeline, ONE __syncthreads per k-iter, 3 CTAs/SM.
//   yBase offsets the M-tile index (for row-slab split launches).
// =====================================================================
#define ROWB 80
#define A_OFF 0
#define B_OFF  (64 * ROWB)              // 5120
#define STAGE_SZ (B_OFF + 128 * ROWB)   // 15360
#define NSTAGE 3
#define SMEM_DYN (NSTAGE * STAGE_SZ)    // 46080

__global__ __launch_bounds__(256, 3) void hmma_gemm(
    const __half* __restrict__ A, const __half* __restrict__ B,
    int kPad, int kTiles, float* __restrict__ C, long cZstride,
    int Nld, int Mreal, int yBase)
{
    extern __shared__ char smraw[];
    const uint32_t sm = smem_u32(smraw);
    const int tid = threadIdx.x;
    const int lane = tid & 31, wid = tid >> 5;
    const int wm = wid & 1, wn = wid >> 1;          // 2 M-warps x 4 N-warps
    const int n0 = blockIdx.x * 128;
    const int m0 = (blockIdx.y + yBase) * 64;
    const int z = blockIdx.z;
    const long k00 = (long)z * kTiles * 32;
    C += (long)z * cZstride;

    const bool act0 = (m0 + wm * 32)      < Mreal;
    const bool act1 = (m0 + wm * 32 + 16) < Mreal;

    const int lrow = tid >> 2, lc = tid & 3;
    const __half* aP  = A + (size_t)(m0 + lrow) * kPad + lc * 8;
    const __half* bP0 = B + (size_t)(n0 + lrow) * kPad + lc * 8;
    const __half* bP1 = B + (size_t)(n0 + 64 + lrow) * kPad + lc * 8;
    const uint32_t aDst  = lrow * ROWB + lc * 16;
    const uint32_t bDst0 = lrow * ROWB + lc * 16;
    const uint32_t bDst1 = (64 + lrow) * ROWB + lc * 16;

    const uint32_t aLdm = sm + (wm * 32 + (lane & 15)) * ROWB + (lane >> 4) * 16;
    const uint32_t bLdm = sm + B_OFF + (wn * 32 + (lane & 15)) * ROWB + (lane >> 4) * 16;

    float d[2][4][4];
#pragma unroll
    for (int mi = 0; mi < 2; ++mi)
#pragma unroll
        for (int ni = 0; ni < 4; ++ni)
#pragma unroll
            for (int q = 0; q < 4; ++q) d[mi][ni][q] = 0.f;

    auto load_stage = [&](int s, int kt) {
        long ke = k00 + (long)kt * 32;
        uint32_t st = sm + s * STAGE_SZ;
        cp16(st + A_OFF + aDst, aP + ke);
        cp16(st + B_OFF + bDst0, bP0 + ke);
        cp16(st + B_OFF + bDst1, bP1 + ke);
        CP_COMMIT();
    };

    load_stage(0, 0);
    load_stage(1, 1);

    int s = 0;
    for (int kt = 0; kt < kTiles; ++kt) {
        if (kt + 1 < kTiles) {
            asm volatile("cp.async.wait_group 1;" ::: "memory");
        } else {
            asm volatile("cp.async.wait_group 0;" ::: "memory");
        }
        __syncthreads();   // single barrier per iteration

        // stage (s+2)%3 was consumed in iter kt-1; all warps are past the
        // barrier above, so refilling it now is race-free.
        if (kt + 2 < kTiles) {
            int s2 = s + 2; if (s2 >= NSTAGE) s2 -= NSTAGE;
            load_stage(s2, kt + 2);
        }

        uint32_t stA = aLdm + s * STAGE_SZ;
        uint32_t stB = bLdm + s * STAGE_SZ;
#pragma unroll
        for (int ks = 0; ks < 2; ++ks) {
            uint32_t ah[2][4], b[2][4];
#pragma unroll
            for (int pr = 0; pr < 2; ++pr)
                LDM4(b[pr], stB + pr * (16 * ROWB) + ks * 32);
            if (act0) LDM4(ah[0], stA + ks * 32);
            if (act1) LDM4(ah[1], stA + 16 * ROWB + ks * 32);
#pragma unroll
            for (int mi = 0; mi < 2; ++mi) {
                if (mi == 0 ? !act0 : !act1) continue;
#pragma unroll
                for (int ni = 0; ni < 4; ++ni) {
                    int pr = ni >> 1, hi = ni & 1;
                    MMA(d[mi][ni], ah[mi], b[pr][hi], b[pr][hi + 2]);
                }
            }
        }
        if (++s == NSTAGE) s = 0;
    }

    // ---- epilogue
#pragma unroll
    for (int mi = 0; mi < 2; ++mi) {
        int r0 = m0 + wm * 32 + mi * 16 + (lane >> 2);
        int r1 = r0 + 8;
#pragma unroll
        for (int ni = 0; ni < 4; ++ni) {
            int col = n0 + wn * 32 + ni * 8 + (lane & 3) * 2;
            if (r0 < Mreal)
                *(float2*)(C + (size_t)r0 * Nld + col) = make_float2(d[mi][ni][0], d[mi][ni][1]);
            if (r1 < Mreal)
                *(float2*)(C + (size_t)r1 * Nld + col) = make_float2(d[mi][ni][2], d[mi][ni][3]);
        }
    }
}

// =====================================================================
// split-K reduce (bandwidth kernel, 832 blocks): fraw = b_emb + sum partials
// =====================================================================
__global__ __launch_bounds__(256) void reduce_feats(
    const float* __restrict__ partial, const float* __restrict__ b_emb,
    float* __restrict__ fraw)
{
    int m = blockIdx.y;
    int c = blockIdx.x * 256 + threadIdx.x;
    float v = b_emb[c];
#pragma unroll
    for (int s = 0; s < KSPLIT; ++s)
        v += partial[((size_t)s * R_TOT + m) * NFB + c];
    fraw[(size_t)m * NFB + c] = v;
}

// =====================================================================
// LayerNorm + ReLU + action head from fraw; emits fp16 feats
// =====================================================================
__global__ __launch_bounds__(256) void ln_act_kernel(
    const float* __restrict__ fraw,
    const float* __restrict__ ln_g, const float* __restrict__ ln_b,
    const float* __restrict__ W_act, const float* __restrict__ b_act,
    __half* __restrict__ fH, float* __restrict__ out_act)
{
    int m = blockIdx.x, tid = threadIdx.x;
    int c = tid * 4;
    int lane = tid & 31, wid = tid >> 5;
    __shared__ float sred[48];

    float4 v = *(const float4*)(fraw + (size_t)m * NFB + c);
    float S = v.x + v.y + v.z + v.w;
    float SS = v.x * v.x + v.y * v.y + v.z * v.z + v.w * v.w;
#pragma unroll
    for (int o = 16; o; o >>= 1) {
        S  += __shfl_down_sync(0xffffffffu, S,  o);
        SS += __shfl_down_sync(0xffffffffu, SS, o);
    }
    if (lane == 0) { sred[wid * 2] = S; sred[wid * 2 + 1] = SS; }
    __syncthreads();
    float tS = 0.f, tSS = 0.f;
#pragma unroll
    for (int w = 0; w < 8; ++w) { tS += sred[w * 2]; tSS += sred[w * 2 + 1]; }
    float mean = tS * (1.0f / NFB);
    float var  = tSS * (1.0f / NFB) - mean * mean;
    float rstd = rsqrtf(var + 1e-5f);

    float4 g = *(const float4*)(ln_g + c);
    float4 bb = *(const float4*)(ln_b + c);
    float f0 = fmaxf((v.x - mean) * rstd * g.x + bb.x, 0.f);
    float f1 = fmaxf((v.y - mean) * rstd * g.y + bb.y, 0.f);
    float f2 = fmaxf((v.z - mean) * rstd * g.z + bb.z, 0.f);
    float f3 = fmaxf((v.w - mean) * rstd * g.w + bb.w, 0.f);

    size_t fo = (size_t)m * NFB + c;
    *(__half2*)(fH + fo)     = __halves2half2(__float2half_rn(f0), __float2half_rn(f1));
    *(__half2*)(fH + fo + 2) = __halves2half2(__float2half_rn(f2), __float2half_rn(f3));

    float a[NA];
#pragma unroll
    for (int o = 0; o < NA; ++o) {
        float4 w = *(const float4*)(W_act + (size_t)o * NFB + c);
        a[o] = f0 * w.x + f1 * w.y + f2 * w.z + f3 * w.w;
    }
    __syncthreads();
#pragma unroll
    for (int o = 0; o < NA; ++o) {
#pragma unroll
        for (int s = 16; s; s >>= 1) a[o] += __shfl_down_sync(0xffffffffu, a[o], s);
        if (lane == 0) sred[wid * NA + o] = a[o];
    }
    __syncthreads();
    if (tid < NA) {
        float s = 0.f;
#pragma unroll
        for (int w = 0; w < 8; ++w) s += sred[w * NA + tid];
        out_act[m * NA + tid] = s + b_act[tid];
    }
}

// =====================================================================
// UV split-K reduce
// =====================================================================
__global__ __launch_bounds__(256) void uv_reduce(
    const float* __restrict__ part, float* __restrict__ out)
{
    size_t i = ((size_t)blockIdx.x * 256 + threadIdx.x) * 4;
    float4 v = *(const float4*)(part + i);
#pragma unroll
    for (int s = 1; s < KSPLIT_U; ++s) {
        float4 p = *(const float4*)(part + (size_t)s * R_TOT * 2 * NFB + i);
        v.x += p.x; v.y += p.y; v.z += p.z; v.w += p.w;
    }
    *(float4*)(out + i) = v;
}

// =====================================================================
// pairwise interaction from U/V (UV layout [208][2048], V at col 1024)
// =====================================================================
__global__ __launch_bounds__(256) void pair_kernel(
    const float* __restrict__ UV, const float* __restrict__ b_i1,
    const float* __restrict__ W_i2, const float* __restrict__ b_i2,
    float* __restrict__ out)
{
    int p = blockIdx.x;
    int b = p / NPAIR_B, q = p % NPAIR_B;
    int i = q / (MAXN - 1), jj = q % (MAXN - 1);
    int j = jj + (jj >= i ? 1 : 0);
    const float* U = UV + (size_t)(b * MAXN + i) * (2 * NFB);
    const float* V = UV + (size_t)(b * MAXN + j) * (2 * NFB) + NFB;

    int tid = threadIdx.x, lane = tid & 31, wid = tid >> 5;
    int c = tid * 4;
    __shared__ float sred[16];

    float4 u  = *(const float4*)(U + c);
    float4 v  = *(const float4*)(V + c);
    float4 bi = *(const float4*)(b_i1 + c);
    float4 w0 = *(const float4*)(W_i2 + c);
    float4 w1 = *(const float4*)(W_i2 + NFB + c);

    float t0 = fmaxf(u.x + v.x + bi.x, 0.f);
    float t1 = fmaxf(u.y + v.y + bi.y, 0.f);
    float t2 = fmaxf(u.z + v.z + bi.z, 0.f);
    float t3 = fmaxf(u.w + v.w + bi.w, 0.f);
    float a0 = t0 * w0.x + t1 * w0.y + t2 * w0.z + t3 * w0.w;
    float a1 = t0 * w1.x + t1 * w1.y + t2 * w1.z + t3 * w1.w;
#pragma unroll
    for (int s = 16; s; s >>= 1) {
        a0 += __shfl_down_sync(0xffffffffu, a0, s);
        a1 += __shfl_down_sync(0xffffffffu, a1, s);
    }
    if (lane == 0) { sred[wid * 2] = a0; sred[wid * 2 + 1] = a1; }
    __syncthreads();
    if (tid < 2) {
        float s = 0.f;
#pragma unroll
        for (int w = 0; w < 8; ++w) s += sred[w * 2 + tid];
        out[p * 2 + tid] = s + b_i2[tid];
    }
}

// =====================================================================
// launch (row-slab overlap of roi-align with GEMM half 1)
// =====================================================================
extern "C" void kernel_launch(void* const* d_in, const int* in_sizes, int n_in,
                              void* d_out, int out_size)
{
    const float* features = (const float*)d_in[0];
    const float* boxes    = (const float*)d_in[1];
    const float* W_emb = (const float*)d_in[3];
    const float* b_emb = (const float*)d_in[4];
    const float* ln_g  = (const float*)d_in[5];
    const float* ln_b  = (const float*)d_in[6];
    const float* W_act = (const float*)d_in[7];
    const float* b_act = (const float*)d_in[8];
    const float* W_i1  = (const float*)d_in[9];
    const float* b_i1  = (const float*)d_in[10];
    const float* W_i2  = (const float*)d_in[11];
    const float* b_i2  = (const float*)d_in[12];
    float* out = (float*)d_out;

    void *ae, *be, *bu, *fh, *fr, *pp, *uvpp, *uvp;
    cudaGetSymbolAddress(&ae, g_Ae);  cudaGetSymbolAddress(&be, g_Be);
    cudaGetSymbolAddress(&bu, g_Bu);  cudaGetSymbolAddress(&fh, g_f);
    cudaGetSymbolAddress(&fr, g_fraw);
    cudaGetSymbolAddress(&pp, g_part); cudaGetSymbolAddress(&uvpp, g_UVp);
    cudaGetSymbolAddress(&uvp, g_UV);

    static cudaStream_t s1 = nullptr, s2 = nullptr, s3 = nullptr;
    static cudaEvent_t evFork = nullptr, evWemb = nullptr, evWi1 = nullptr;
    static cudaEvent_t evRoiA = nullptr, evG1 = nullptr;
    if (!s1) {
        cudaFuncSetAttribute(hmma_gemm, cudaFuncAttributeMaxDynamicSharedMemorySize, SMEM_DYN);
        cudaStreamCreateWithFlags(&s1, cudaStreamNonBlocking);
        cudaStreamCreateWithFlags(&s2, cudaStreamNonBlocking);
        cudaStreamCreateWithFlags(&s3, cudaStreamNonBlocking);
        cudaEventCreateWithFlags(&evFork, cudaEventDisableTiming);
        cudaEventCreateWithFlags(&evWemb, cudaEventDisableTiming);
        cudaEventCreateWithFlags(&evWi1,  cudaEventDisableTiming);
        cudaEventCreateWithFlags(&evRoiA, cudaEventDisableTiming);
        cudaEventCreateWithFlags(&evG1,   cudaEventDisableTiming);
    }

    // ---- fork: weight conversions on side streams
    cudaEventRecord(evFork, 0);
    cudaStreamWaitEvent(s1, evFork, 0);
    cudaStreamWaitEvent(s2, evFork, 0);

    conv_wemb<<<dim3(KPAD_E / 2048, NFB), 256, 0, s1>>>(W_emb, (__half*)be);
    cudaEventRecord(evWemb, s1);
    conv_wi1<<<2 * NFB, 128, 0, s2>>>(W_i1, (__half*)bu);
    cudaEventRecord(evWi1, s2);

    // ---- roi-align, row slab A (rows 0..127) then slab B (rows 128..207)
    roi_align_kernel<<<dim3(D_CH / 32, RSPLIT), 256>>>(features, boxes, (__half*)ae, 0);
    cudaEventRecord(evRoiA, 0);
    roi_align_kernel<<<dim3(D_CH / 32, R_TOT - RSPLIT), 256>>>(features, boxes,
                                                               (__half*)ae, RSPLIT);

    // ---- GEMM half 1 (M-tiles 0,1 = rows 0..127) on s3, overlaps roi slab B
    cudaStreamWaitEvent(s3, evRoiA, 0);
    cudaStreamWaitEvent(s3, evWemb, 0);
    hmma_gemm<<<dim3(NFB / 128, 2, KSPLIT), 256, SMEM_DYN, s3>>>(
        (const __half*)ae, (const __half*)be,
        KPAD_E, KT_E, (float*)pp, (long)R_TOT * NFB, NFB, R_TOT, 0);
    cudaEventRecord(evG1, s3);

    // ---- GEMM half 2 (M-tiles 2,3 = rows 128..207) on main after roi slab B
    cudaStreamWaitEvent(0, evWemb, 0);
    hmma_gemm<<<dim3(NFB / 128, 2, KSPLIT), 256, SMEM_DYN>>>(
        (const __half*)ae, (const __half*)be,
        KPAD_E, KT_E, (float*)pp, (long)R_TOT * NFB, NFB, R_TOT, 2);

    // ---- join half 1, then reduce + LN + action head
    cudaStreamWaitEvent(0, evG1, 0);
    reduce_feats<<<dim3(NFB / 256, R_TOT), 256>>>((const float*)pp, b_emb, (float*)fr);
    ln_act_kernel<<<R_TOT, 256>>>((const float*)fr, ln_g, ln_b, W_act, b_act,
                                  (__half*)fh, out);

    // ---- UV GEMM
    cudaStreamWaitEvent(0, evWi1, 0);
    hmma_gemm<<<dim3(2 * NFB / 128, 4, KSPLIT_U), 256, SMEM_DYN>>>(
        (const __half*)fh, (const __half*)bu,
        KPAD_U, KT_U, (float*)uvpp, (long)R_TOT * 2 * NFB, 2 * NFB, R_TOT, 0);
    uv_reduce<<<(R_TOT * 2 * NFB) / (256 * 4), 256>>>((const float*)uvpp, (float*)uvp);

    // pairwise combine + interaction head
    pair_kernel<<<NPAIR, 256>>>((const float*)uvp, b_i1, W_i2, b_i2, out + R_TOT * NA);
}

// round 17
// speedup vs baseline: 1.0520x; 1.0520x over previous
#include <cuda_runtime.h>
#include <cuda_fp16.h>
#include <cstdint>

// ---------------- problem constants ----------------
#define BT    16
#define D_CH  1056
#define OH    57
#define OW    87
#define MAXN  13
#define KK    5
#define NFB   1024
#define NA    6
#define R_TOT 208
#define KDIM  26400
#define KPAD_E 26624              // 832 * 32
#define KSPLIT 32
#define KT_E   (KPAD_E/32/KSPLIT) // 26 k-chunks (of 32) per split
#define KPAD_U 1024
#define KSPLIT_U 4
#define KT_U   (KPAD_U/32/KSPLIT_U) // 8
#define NPAIR_B 156
#define NPAIR   2496
#define MROWS 256

// ---------------- scratch (device globals; zero-initialized) ----------------
__device__ __align__(16) __half g_Ae [MROWS * KPAD_E];
__device__ __align__(16) __half g_Be [NFB * KPAD_E];
__device__ __align__(16) __half g_Bu [2 * NFB * KPAD_U];
__device__ __align__(16) __half g_f  [MROWS * NFB];
__device__ float g_part[KSPLIT * R_TOT * NFB];
__device__ float g_UVp [KSPLIT_U * R_TOT * 2 * NFB];
__device__ float g_UV  [R_TOT * 2 * NFB];

// ---------------- helpers ----------------
__device__ __forceinline__ uint32_t smem_u32(const void* p) {
    uint32_t a;
    asm("{ .reg .u64 t; cvta.to.shared.u64 t, %1; cvt.u32.u64 %0, t; }"
        : "=r"(a) : "l"(p));
    return a;
}
__device__ __forceinline__ void cp16(uint32_t dst, const void* src) {
    asm volatile("cp.async.cg.shared.global [%0], [%1], 16;" :: "r"(dst), "l"(src));
}
#define CP_COMMIT() asm volatile("cp.async.commit_group;" ::: "memory")

#define LDM4(R, addr) \
    asm volatile("ldmatrix.sync.aligned.m8n8.x4.shared.b16 {%0,%1,%2,%3}, [%4];" \
        : "=r"((R)[0]), "=r"((R)[1]), "=r"((R)[2]), "=r"((R)[3]) : "r"(addr))

#define MMA(D, A, B0, B1) \
    asm volatile("mma.sync.aligned.m16n8k16.row.col.f32.f16.f16.f32 " \
        "{%0,%1,%2,%3}, {%4,%5,%6,%7}, {%8,%9}, {%0,%1,%2,%3};" \
        : "+f"((D)[0]), "+f"((D)[1]), "+f"((D)[2]), "+f"((D)[3]) \
        : "r"((A)[0]), "r"((A)[1]), "r"((A)[2]), "r"((A)[3]), "r"(B0), "r"(B1))

// =====================================================================
// converters (vectorized: 8 elems/thread, 16B stores)
// =====================================================================
__global__ __launch_bounds__(256) void conv_wemb(
    const float* __restrict__ W, __half* __restrict__ o)
{
    int f = blockIdx.y;
    int k0 = (blockIdx.x * 256 + threadIdx.x) * 8;   // grid.x = 13
    __half h[8];
    const float* src = W + (size_t)f * KDIM + k0;
    if (k0 + 8 <= KDIM) {
        float4 v0 = *(const float4*)src;
        float4 v1 = *(const float4*)(src + 4);
        h[0] = __float2half_rn(v0.x); h[1] = __float2half_rn(v0.y);
        h[2] = __float2half_rn(v0.z); h[3] = __float2half_rn(v0.w);
        h[4] = __float2half_rn(v1.x); h[5] = __float2half_rn(v1.y);
        h[6] = __float2half_rn(v1.z); h[7] = __float2half_rn(v1.w);
    } else {
#pragma unroll
        for (int i = 0; i < 8; ++i)
            h[i] = (k0 + i < KDIM) ? __float2half_rn(src[i]) : __ushort_as_half(0);
    }
    *(uint4*)(o + (size_t)f * KPAD_E + k0) = *(const uint4*)h;
}

__global__ __launch_bounds__(128) void conv_wi1(
    const float* __restrict__ W, __half* __restrict__ o)
{
    int f = blockIdx.x;
    int k0 = threadIdx.x * 8;
    const float* src = (f < NFB) ? W + (size_t)f * (2 * NFB) + k0
                                 : W + (size_t)(f - NFB) * (2 * NFB) + NFB + k0;
    float4 v0 = *(const float4*)src;
    float4 v1 = *(const float4*)(src + 4);
    __half h[8];
    h[0] = __float2half_rn(v0.x); h[1] = __float2half_rn(v0.y);
    h[2] = __float2half_rn(v0.z); h[3] = __float2half_rn(v0.w);
    h[4] = __float2half_rn(v1.x); h[5] = __float2half_rn(v1.y);
    h[6] = __float2half_rn(v1.z); h[7] = __float2half_rn(v1.w);
    *(uint4*)(o + (size_t)f * KPAD_U + k0) = *(const uint4*)h;
}

// =====================================================================
// ROI align -> fp16 A operand (point math hoisted to 25 threads)
// =====================================================================
__global__ __launch_bounds__(256) void roi_align_kernel(
    const float* __restrict__ feat, const float* __restrict__ boxes,
    __half* __restrict__ ah)
{
    int r  = blockIdx.y;
    int d0 = blockIdx.x * 32;
    int b  = r / MAXN;
    int tid = threadIdx.x;

    __shared__ int4   sidx[25];
    __shared__ float4 swgt[25];
    __shared__ float  tile[32][25];

    if (tid < 25) {
        const float* bx = boxes + r * 4;
        float x1 = bx[0], y1 = bx[1], x2 = bx[2], y2 = bx[3];
        float bw = (x2 - x1) * (1.0f / KK);
        float bh = (y2 - y1) * (1.0f / KK);
        int iy = tid / 5, jx = tid % 5;
        float xs = x1 + (jx + 0.5f) * bw;
        float ys = y1 + (iy + 0.5f) * bh;
        float x0f = floorf(xs), y0f = floorf(ys);
        float lx = xs - x0f, ly = ys - y0f;
        int x0 = (int)x0f, y0 = (int)y0f;
        int x0i = min(max(x0, 0), OW - 1);
        int x1i = min(max(x0 + 1, 0), OW - 1);
        int y0i = min(max(y0, 0), OH - 1);
        int y1i = min(max(y0 + 1, 0), OH - 1);
        sidx[tid] = make_int4(y0i * OW + x0i, y0i * OW + x1i,
                              y1i * OW + x0i, y1i * OW + x1i);
        float wy0 = 1.f - ly, wx0 = 1.f - lx;
        swgt[tid] = make_float4(wy0 * wx0, wy0 * lx, ly * wx0, ly * lx);
    }
    __syncthreads();

    int dl = tid >> 3, pl = tid & 7;
    const float* fb = feat + (size_t)(b * D_CH + d0 + dl) * (OH * OW);
    for (int p = pl; p < 25; p += 8) {
        int4 ix = sidx[p];
        float4 w = swgt[p];
        tile[dl][p] = fb[ix.x] * w.x + fb[ix.y] * w.y
                    + fb[ix.z] * w.z + fb[ix.w] * w.w;
    }
    __syncthreads();

    size_t base = (size_t)r * KPAD_E + d0 * 25;  // even offset
    const float* src = &tile[0][0];
    for (int t = tid; t < 400; t += 256) {
        *(__half2*)(ah + base + 2 * t) =
            __halves2half2(__float2half_rn(src[2 * t]), __float2half_rn(src[2 * t + 1]));
    }
    if (blockIdx.x == 0 && tid < 28) {
        uint4 z = make_uint4(0, 0, 0, 0);
        *(uint4*)(ah + (size_t)r * KPAD_E + KDIM + tid * 8) = z;
    }
}

// =====================================================================
// HMMA fp16 GEMM (R11 measured-best config): C[z] = A * B^T
//   block tile 64(M) x 128(N) x 32(K), 8 warps (2M x 4N, warp tile 32x32),
//   3-stage cp.async pipeline, ONE __syncthreads per k-iter, 3 CTAs/SM
// =====================================================================
#define ROWB 80
#define A_OFF 0
#define B_OFF  (64 * ROWB)              // 5120
#define STAGE_SZ (B_OFF + 128 * ROWB)   // 15360
#define NSTAGE 3
#define SMEM_DYN (NSTAGE * STAGE_SZ)    // 46080

__global__ __launch_bounds__(256, 3) void hmma_gemm(
    const __half* __restrict__ A, const __half* __restrict__ B,
    int kPad, int kTiles, float* __restrict__ C, long cZstride,
    int Nld, int Mreal)
{
    extern __shared__ char smraw[];
    const uint32_t sm = smem_u32(smraw);
    const int tid = threadIdx.x;
    const int lane = tid & 31, wid = tid >> 5;
    const int wm = wid & 1, wn = wid >> 1;          // 2 M-warps x 4 N-warps
    const int n0 = blockIdx.x * 128, m0 = blockIdx.y * 64, z = blockIdx.z;
    const long k00 = (long)z * kTiles * 32;
    C += (long)z * cZstride;

    const bool act0 = (m0 + wm * 32)      < Mreal;
    const bool act1 = (m0 + wm * 32 + 16) < Mreal;

    const int lrow = tid >> 2, lc = tid & 3;
    const __half* aP  = A + (size_t)(m0 + lrow) * kPad + lc * 8;
    const __half* bP0 = B + (size_t)(n0 + lrow) * kPad + lc * 8;
    const __half* bP1 = B + (size_t)(n0 + 64 + lrow) * kPad + lc * 8;
    const uint32_t aDst  = lrow * ROWB + lc * 16;
    const uint32_t bDst0 = lrow * ROWB + lc * 16;
    const uint32_t bDst1 = (64 + lrow) * ROWB + lc * 16;

    const uint32_t aLdm = sm + (wm * 32 + (lane & 15)) * ROWB + (lane >> 4) * 16;
    const uint32_t bLdm = sm + B_OFF + (wn * 32 + (lane & 15)) * ROWB + (lane >> 4) * 16;

    float d[2][4][4];
#pragma unroll
    for (int mi = 0; mi < 2; ++mi)
#pragma unroll
        for (int ni = 0; ni < 4; ++ni)
#pragma unroll
            for (int q = 0; q < 4; ++q) d[mi][ni][q] = 0.f;

    auto load_stage = [&](int s, int kt) {
        long ke = k00 + (long)kt * 32;
        uint32_t st = sm + s * STAGE_SZ;
        cp16(st + A_OFF + aDst, aP + ke);
        cp16(st + B_OFF + bDst0, bP0 + ke);
        cp16(st + B_OFF + bDst1, bP1 + ke);
        CP_COMMIT();
    };

    load_stage(0, 0);
    load_stage(1, 1);

    int s = 0;
    for (int kt = 0; kt < kTiles; ++kt) {
        if (kt + 1 < kTiles) {
            asm volatile("cp.async.wait_group 1;" ::: "memory");
        } else {
            asm volatile("cp.async.wait_group 0;" ::: "memory");
        }
        __syncthreads();   // single barrier per iteration

        // stage (s+2)%3 was consumed in iter kt-1; all warps are past the
        // barrier above, so refilling it now is race-free.
        if (kt + 2 < kTiles) {
            int s2 = s + 2; if (s2 >= NSTAGE) s2 -= NSTAGE;
            load_stage(s2, kt + 2);
        }

        uint32_t stA = aLdm + s * STAGE_SZ;
        uint32_t stB = bLdm + s * STAGE_SZ;
#pragma unroll
        for (int ks = 0; ks < 2; ++ks) {
            uint32_t ah[2][4], b[2][4];
#pragma unroll
            for (int pr = 0; pr < 2; ++pr)
                LDM4(b[pr], stB + pr * (16 * ROWB) + ks * 32);
            if (act0) LDM4(ah[0], stA + ks * 32);
            if (act1) LDM4(ah[1], stA + 16 * ROWB + ks * 32);
#pragma unroll
            for (int mi = 0; mi < 2; ++mi) {
                if (mi == 0 ? !act0 : !act1) continue;
#pragma unroll
                for (int ni = 0; ni < 4; ++ni) {
                    int pr = ni >> 1, hi = ni & 1;
                    MMA(d[mi][ni], ah[mi], b[pr][hi], b[pr][hi + 2]);
                }
            }
        }
        if (++s == NSTAGE) s = 0;
    }

    // ---- epilogue
#pragma unroll
    for (int mi = 0; mi < 2; ++mi) {
        int r0 = m0 + wm * 32 + mi * 16 + (lane >> 2);
        int r1 = r0 + 8;
#pragma unroll
        for (int ni = 0; ni < 4; ++ni) {
            int col = n0 + wn * 32 + ni * 8 + (lane & 3) * 2;
            if (r0 < Mreal)
                *(float2*)(C + (size_t)r0 * Nld + col) = make_float2(d[mi][ni][0], d[mi][ni][1]);
            if (r1 < Mreal)
                *(float2*)(C + (size_t)r1 * Nld + col) = make_float2(d[mi][ni][2], d[mi][ni][3]);
        }
    }
}

// =====================================================================
// split-K reduce + bias + LayerNorm + ReLU + action head; emits fp16.
//   512 threads, 2 cols/thread: 2x warps vs R11 to hide the 27MB
//   partial-read latency (R13 profile: occ 17%, issue 8%).
// =====================================================================
__global__ __launch_bounds__(512) void ln_act_kernel(
    const float* __restrict__ partial, const float* __restrict__ b_emb,
    const float* __restrict__ ln_g, const float* __restrict__ ln_b,
    const float* __restrict__ W_act, const float* __restrict__ b_act,
    __half* __restrict__ fH, float* __restrict__ out_act)
{
    int m = blockIdx.x, tid = threadIdx.x;
    int c = tid * 2;
    int lane = tid & 31, wid = tid >> 5;   // 16 warps
    __shared__ float sred[96];

    float2 v = *(const float2*)(b_emb + c);
#pragma unroll
    for (int s = 0; s < KSPLIT; ++s) {
        float2 p = *(const float2*)(partial + ((size_t)s * R_TOT + m) * NFB + c);
        v.x += p.x; v.y += p.y;
    }
    float S  = v.x + v.y;
    float SS = v.x * v.x + v.y * v.y;
#pragma unroll
    for (int o = 16; o; o >>= 1) {
        S  += __shfl_down_sync(0xffffffffu, S,  o);
        SS += __shfl_down_sync(0xffffffffu, SS, o);
    }
    if (lane == 0) { sred[wid * 2] = S; sred[wid * 2 + 1] = SS; }
    __syncthreads();
    float tS = 0.f, tSS = 0.f;
#pragma unroll
    for (int w = 0; w < 16; ++w) { tS += sred[w * 2]; tSS += sred[w * 2 + 1]; }
    float mean = tS * (1.0f / NFB);
    float var  = tSS * (1.0f / NFB) - mean * mean;
    float rstd = rsqrtf(var + 1e-5f);

    float2 g  = *(const float2*)(ln_g + c);
    float2 bb = *(const float2*)(ln_b + c);
    float f0 = fmaxf((v.x - mean) * rstd * g.x + bb.x, 0.f);
    float f1 = fmaxf((v.y - mean) * rstd * g.y + bb.y, 0.f);

    size_t fo = (size_t)m * NFB + c;
    *(__half2*)(fH + fo) = __halves2half2(__float2half_rn(f0), __float2half_rn(f1));

    float a[NA];
#pragma unroll
    for (int o = 0; o < NA; ++o) {
        float2 w = *(const float2*)(W_act + (size_t)o * NFB + c);
        a[o] = f0 * w.x + f1 * w.y;
    }
    __syncthreads();
#pragma unroll
    for (int o = 0; o < NA; ++o) {
#pragma unroll
        for (int s = 16; s; s >>= 1) a[o] += __shfl_down_sync(0xffffffffu, a[o], s);
        if (lane == 0) sred[wid * NA + o] = a[o];
    }
    __syncthreads();
    if (tid < NA) {
        float s = 0.f;
#pragma unroll
        for (int w = 0; w < 16; ++w) s += sred[w * NA + tid];
        out_act[m * NA + tid] = s + b_act[tid];
    }
}

// =====================================================================
// UV split-K reduce
// =====================================================================
__global__ __launch_bounds__(256) void uv_reduce(
    const float* __restrict__ part, float* __restrict__ out)
{
    size_t i = ((size_t)blockIdx.x * 256 + threadIdx.x) * 4;
    float4 v = *(const float4*)(part + i);
#pragma unroll
    for (int s = 1; s < KSPLIT_U; ++s) {
        float4 p = *(const float4*)(part + (size_t)s * R_TOT * 2 * NFB + i);
        v.x += p.x; v.y += p.y; v.z += p.z; v.w += p.w;
    }
    *(float4*)(out + i) = v;
}

// =====================================================================
// pairwise interaction from U/V (UV layout [208][2048], V at col 1024)
// =====================================================================
__global__ __launch_bounds__(256) void pair_kernel(
    const float* __restrict__ UV, const float* __restrict__ b_i1,
    const float* __restrict__ W_i2, const float* __restrict__ b_i2,
    float* __restrict__ out)
{
    int p = blockIdx.x;
    int b = p / NPAIR_B, q = p % NPAIR_B;
    int i = q / (MAXN - 1), jj = q % (MAXN - 1);
    int j = jj + (jj >= i ? 1 : 0);
    const float* U = UV + (size_t)(b * MAXN + i) * (2 * NFB);
    const float* V = UV + (size_t)(b * MAXN + j) * (2 * NFB) + NFB;

    int tid = threadIdx.x, lane = tid & 31, wid = tid >> 5;
    int c = tid * 4;
    __shared__ float sred[16];

    float4 u  = *(const float4*)(U + c);
    float4 v  = *(const float4*)(V + c);
    float4 bi = *(const float4*)(b_i1 + c);
    float4 w0 = *(const float4*)(W_i2 + c);
    float4 w1 = *(const float4*)(W_i2 + NFB + c);

    float t0 = fmaxf(u.x + v.x + bi.x, 0.f);
    float t1 = fmaxf(u.y + v.y + bi.y, 0.f);
    float t2 = fmaxf(u.z + v.z + bi.z, 0.f);
    float t3 = fmaxf(u.w + v.w + bi.w, 0.f);
    float a0 = t0 * w0.x + t1 * w0.y + t2 * w0.z + t3 * w0.w;
    float a1 = t0 * w1.x + t1 * w1.y + t2 * w1.z + t3 * w1.w;
#pragma unroll
    for (int s = 16; s; s >>= 1) {
        a0 += __shfl_down_sync(0xffffffffu, a0, s);
        a1 += __shfl_down_sync(0xffffffffu, a1, s);
    }
    if (lane == 0) { sred[wid * 2] = a0; sred[wid * 2 + 1] = a1; }
    __syncthreads();
    if (tid < 2) {
        float s = 0.f;
#pragma unroll
        for (int w = 0; w < 8; ++w) s += sred[w * 2 + tid];
        out[p * 2 + tid] = s + b_i2[tid];
    }
}

// =====================================================================
// launch (multi-stream fork/join, graph-capturable) — R11 structure
// =====================================================================
extern "C" void kernel_launch(void* const* d_in, const int* in_sizes, int n_in,
                              void* d_out, int out_size)
{
    const float* features = (const float*)d_in[0];
    const float* boxes    = (const float*)d_in[1];
    const float* W_emb = (const float*)d_in[3];
    const float* b_emb = (const float*)d_in[4];
    const float* ln_g  = (const float*)d_in[5];
    const float* ln_b  = (const float*)d_in[6];
    const float* W_act = (const float*)d_in[7];
    const float* b_act = (const float*)d_in[8];
    const float* W_i1  = (const float*)d_in[9];
    const float* b_i1  = (const float*)d_in[10];
    const float* W_i2  = (const float*)d_in[11];
    const float* b_i2  = (const float*)d_in[12];
    float* out = (float*)d_out;

    void *ae, *be, *bu, *fh, *pp, *uvpp, *uvp;
    cudaGetSymbolAddress(&ae, g_Ae);  cudaGetSymbolAddress(&be, g_Be);
    cudaGetSymbolAddress(&bu, g_Bu);  cudaGetSymbolAddress(&fh, g_f);
    cudaGetSymbolAddress(&pp, g_part); cudaGetSymbolAddress(&uvpp, g_UVp);
    cudaGetSymbolAddress(&uvp, g_UV);

    static cudaStream_t s1 = nullptr, s2 = nullptr;
    static cudaEvent_t evFork = nullptr, evWemb = nullptr, evWi1 = nullptr;
    if (!s1) {
        cudaFuncSetAttribute(hmma_gemm, cudaFuncAttributeMaxDynamicSharedMemorySize, SMEM_DYN);
        cudaStreamCreateWithFlags(&s1, cudaStreamNonBlocking);
        cudaStreamCreateWithFlags(&s2, cudaStreamNonBlocking);
        cudaEventCreateWithFlags(&evFork, cudaEventDisableTiming);
        cudaEventCreateWithFlags(&evWemb, cudaEventDisableTiming);
        cudaEventCreateWithFlags(&evWi1,  cudaEventDisableTiming);
    }

    // ---- fork: roi-align first on the critical path, conversions on sides
    cudaEventRecord(evFork, 0);
    cudaStreamWaitEvent(s1, evFork, 0);
    cudaStreamWaitEvent(s2, evFork, 0);

    roi_align_kernel<<<dim3(D_CH / 32, R_TOT), 256>>>(features, boxes, (__half*)ae);

    conv_wemb<<<dim3(KPAD_E / 2048, NFB), 256, 0, s1>>>(W_emb, (__half*)be);
    cudaEventRecord(evWemb, s1);
    conv_wi1<<<2 * NFB, 128, 0, s2>>>(W_i1, (__half*)bu);
    cudaEventRecord(evWi1, s2);

    // ---- join W_emb, single 1024-CTA embedding GEMM (R11 config)
    cudaStreamWaitEvent(0, evWemb, 0);
    hmma_gemm<<<dim3(NFB / 128, 4, KSPLIT), 256, SMEM_DYN>>>(
        (const __half*)ae, (const __half*)be,
        KPAD_E, KT_E, (float*)pp, (long)R_TOT * NFB, NFB, R_TOT);

    // reduce + LN + ReLU + action head (512-thread variant)
    ln_act_kernel<<<R_TOT, 512>>>((const float*)pp, b_emb, ln_g, ln_b, W_act, b_act,
                                  (__half*)fh, out);

    // ---- UV GEMM (R11 config)
    cudaStreamWaitEvent(0, evWi1, 0);
    hmma_gemm<<<dim3(2 * NFB / 128, 4, KSPLIT_U), 256, SMEM_DYN>>>(
        (const __half*)fh, (const __half*)bu,
        KPAD_U, KT_U, (float*)uvpp, (long)R_TOT * 2 * NFB, 2 * NFB, R_TOT);
    uv_reduce<<<(R_TOT * 2 * NFB) / (256 * 4), 256>>>((const float*)uvpp, (float*)uvp);

    // pairwise combine + interaction head
    pair_kernel<<<NPAIR, 256>>>((const float*)uvp, b_i1, W_i2, b_i2, out + R_TOT * NA);
}